// round 12
// baseline (speedup 1.0000x reference)
#include <cuda_runtime.h>
#include <cuda_fp16.h>
#include <cstdint>

// Problem constants
#define DD    512
#define TT    192
#define NNODE 64
#define BB    8
#define HH    8
#define DHH   64
#define CC    8
#define M_TOTAL (BB*TT*NNODE)   // 98304
#define BT (BB*TT)              // 1536

// ---------------- scratch (allocation-free: __device__ globals) ----------------
__device__ int   g_cid[NNODE];
// activations: fp16 hi/lo split (A-side of GEMMs needs hi+lo; B-side hi only)
__device__ __half g_Xhi[(size_t)M_TOTAL * DD];
__device__ __half g_Xlo[(size_t)M_TOTAL * DD];
__device__ __half g_Qhi[(size_t)M_TOTAL * DD];
__device__ __half g_Qlo[(size_t)M_TOTAL * DD];
__device__ __half g_Khi[(size_t)M_TOTAL * DD];
__device__ __half g_Vhi[(size_t)M_TOTAL * DD];
__device__ __half g_Ohi[(size_t)M_TOTAL * DD];
__device__ __half g_Olo[(size_t)M_TOTAL * DD];
// weights, fp16 (hi only): [0]=Wq, [1]=Wv, [2]=proj (K-major, W[e][d]),
// [3+c] = Wk[c] transposed to K-major
#define NW 11
__device__ __half g_Wh[(size_t)NW * DD * DD];

// ================= PTX helpers (NO arch-'a' instructions: sm_80-safe) ==========
__device__ __forceinline__ uint32_t smem_u32(const void* p) {
    uint32_t a;
    asm("{ .reg .u64 t; cvta.to.shared.u64 t, %1; cvt.u32.u64 %0, t; }" : "=r"(a) : "l"(p));
    return a;
}
#define CP16(saddr, gptr) \
    asm volatile("cp.async.cg.shared.global [%0], [%1], 16;" \
        :: "r"((uint32_t)(saddr)), "l"(gptr))
#define CP_COMMIT() asm volatile("cp.async.commit_group;")
#define CP_WAIT(n)  asm volatile("cp.async.wait_group %0;" :: "n"(n))
#define LDSM4(r, addr) \
    asm volatile("ldmatrix.sync.aligned.m8n8.x4.shared.b16 {%0,%1,%2,%3}, [%4];" \
        : "=r"((r)[0]), "=r"((r)[1]), "=r"((r)[2]), "=r"((r)[3]) : "r"((uint32_t)(addr)))
#define LDSM4T(r, addr) \
    asm volatile("ldmatrix.sync.aligned.m8n8.x4.trans.shared.b16 {%0,%1,%2,%3}, [%4];" \
        : "=r"((r)[0]), "=r"((r)[1]), "=r"((r)[2]), "=r"((r)[3]) : "r"((uint32_t)(addr)))
#define MMAH(d, a, b) \
    asm volatile("mma.sync.aligned.m16n8k16.row.col.f32.f16.f16.f32 " \
        "{%0,%1,%2,%3}, {%4,%5,%6,%7}, {%8,%9}, {%0,%1,%2,%3};" \
        : "+f"((d)[0]), "+f"((d)[1]), "+f"((d)[2]), "+f"((d)[3]) \
        : "r"((a)[0]), "r"((a)[1]), "r"((a)[2]), "r"((a)[3]), \
          "r"((b)[0]), "r"((b)[1]))

__device__ __forceinline__ void hiloh(float v, uint32_t& h, uint32_t& l) {
    __half hb = __float2half_rn(v);
    h = (uint32_t)__half_as_ushort(hb);
    l = (uint32_t)__half_as_ushort(__float2half_rn(v - __half2float(hb)));
}
__device__ __forceinline__ void hilo2h(float v0, float v1, uint32_t& hp, uint32_t& lp) {
    uint32_t h0, l0, h1, l1;
    hiloh(v0, h0, l0); hiloh(v1, h1, l1);
    hp = h0 | (h1 << 16);
    lp = l0 | (l1 << 16);
}

// ---------------- cluster-id decode (handles int64 OR int32 payload) ----------
__global__ void decode_cid_kernel(const int* __restrict__ raw) {
    bool is64 = true;
    for (int i = 0; i < 32; i++) if (raw[2*i + 1] != 0) { is64 = false; break; }
    for (int i = 0; i < NNODE; i++) g_cid[i] = is64 ? raw[2*i] : raw[i];
}

// ---------------- weight conversion prepass: fp32 -> fp16 ---------------------
__global__ __launch_bounds__(256) void convert_weights_kernel(
    const float* __restrict__ Wq, const float* __restrict__ Wv,
    const float* __restrict__ proj, const float* __restrict__ Wk)
{
    int idx = blockIdx.x * 256 + threadIdx.x;
    int w = idx >> 18;
    int rc = idx & 262143;
    float v;
    if (w < 3) {
        const float* src = (w == 0) ? Wq : ((w == 1) ? Wv : proj);
        v = src[rc];
    } else {
        int e = rc >> 9, d = rc & 511;
        v = Wk[(((size_t)(w - 3)) * DD + d) * DD + e];   // transpose to K-major
    }
    g_Wh[idx] = __float2half_rn(v);
}

// ---------------- x conversion prepass: fp32 -> fp16 hi/lo --------------------
__global__ __launch_bounds__(256) void convert_x_kernel(const float* __restrict__ x) {
    size_t i = ((size_t)blockIdx.x * 256 + threadIdx.x) * 4;
    float4 v = *reinterpret_cast<const float4*>(x + i);
    uint32_t hp0, lp0, hp1, lp1;
    hilo2h(v.x, v.y, hp0, lp0);
    hilo2h(v.z, v.w, hp1, lp1);
    uint2 hp, lp;
    hp.x = hp0; hp.y = hp1; lp.x = lp0; lp.y = lp1;
    *reinterpret_cast<uint2*>(g_Xhi + i) = hp;
    *reinterpret_cast<uint2*>(g_Xlo + i) = lp;
}

// ================= mma.sync GEMM: C = A @ W^T + bias ===========================
// 2-term fp16 split: (Ahi + Alo) @ Whi. Block 64x128, 8 warps (4m x 2n),
// warp tile 16x64, K-chunk 32, 2-stage cp.async pipeline, 4 CTAs/SM.
// Row stride 80B -> conflict-free ldmatrix.
// OUT: 0 = fp32, 1 = fp16 hi only, 2 = fp16 hi+lo.
#define ROWB 80
#define A_BYTES (64 * ROWB)                  // 5120 per A sub-tensor
#define STG_BYTES (2 * A_BYTES + 128 * ROWB) // 20480 per stage (Ahi, Alo, Bh)
#define SMEM_GEMM (2 * STG_BYTES)            // 40960

template<int GROUPED, int OUT>
__global__ __launch_bounds__(256, 4) void gemm_mma_kernel(
    const __half* __restrict__ Ahi, const __half* __restrict__ Alo,
    const float* __restrict__ bias_plain, const float* __restrict__ bk,
    float* __restrict__ Cf32,
    __half* __restrict__ Chi, __half* __restrict__ Clo,
    int widx)
{
    extern __shared__ char smem[];
    const uint32_t sbase = smem_u32(smem);
    const int tid = threadIdx.x;
    const int lane = tid & 31, wid = tid >> 5;
    const int warp_m = wid & 3;       // 4 m-tiles of 16 rows
    const int warp_n = wid >> 2;      // 2 n-tiles of 64 cols
    const int n0 = blockIdx.x * 128;
    const int m0 = blockIdx.y * 64;

    int nz = 0, cid = 0;
    const __half* Bh;
    if (GROUPED) {
        nz = blockIdx.z;
        cid = g_cid[nz];
        Bh = g_Wh + (size_t)(3 + cid) * DD * DD;
    } else {
        Bh = g_Wh + (size_t)widx * DD * DD;
    }

    float acc[8][4];
    #pragma unroll
    for (int b = 0; b < 8; b++)
        #pragma unroll
        for (int c = 0; c < 4; c++) acc[b][c] = 0.f;

    auto load_chunk = [&](int kc) {
        const int k0 = kc * 32;
        const uint32_t st = sbase + (kc & 1) * STG_BYTES;
        // A: 64 rows x 32 k -> 256 x 16B, one per thread (hi + lo)
        {
            const int row = tid >> 2, c = tid & 3;
            const uint32_t so = (uint32_t)(row * ROWB + c * 16);
            size_t arow = GROUPED ? ((size_t)(m0 + row) * NNODE + nz)
                                  : (size_t)(m0 + row);
            CP16(st + so, Ahi + arow * DD + k0 + c * 8);
            CP16(st + A_BYTES + so, Alo + arow * DD + k0 + c * 8);
        }
        // B: 128 rows x 32 k -> 512 x 16B, two per thread
        #pragma unroll
        for (int i = 0; i < 2; i++) {
            const int u = tid + i * 256;
            const int row = u >> 2, c = u & 3;
            const uint32_t so = (uint32_t)(row * ROWB + c * 16);
            CP16(st + 2 * A_BYTES + so, Bh + (size_t)(n0 + row) * DD + k0 + c * 8);
        }
    };

    load_chunk(0); CP_COMMIT();

    for (int kc = 0; kc < 16; kc++) {
        CP_WAIT(0);              // chunk kc resident
        __syncthreads();         // all warps done reading stage (kc+1)&1 from kc-1
        if (kc + 1 < 16) { load_chunk(kc + 1); CP_COMMIT(); }

        const uint32_t sa  = sbase + (kc & 1) * STG_BYTES;
        const uint32_t sal = sa + A_BYTES;
        const uint32_t sb  = sa + 2 * A_BYTES;

        #pragma unroll
        for (int ks = 0; ks < 2; ks++) {
            uint32_t ah[4], al[4], bh[8][2];
            #pragma unroll
            for (int nb = 0; nb < 4; nb++) {
                const uint32_t bo = (uint32_t)((warp_n * 64 + nb * 16 + ((lane >> 4) << 3)
                                                + (lane & 7)) * ROWB
                                               + ks * 32 + ((lane >> 3) & 1) * 16);
                uint32_t r[4];
                LDSM4(r, sb + bo);
                bh[nb*2][0] = r[0]; bh[nb*2][1] = r[1];
                bh[nb*2+1][0] = r[2]; bh[nb*2+1][1] = r[3];
            }
            {
                const uint32_t ao = (uint32_t)((warp_m * 16 + (lane & 15)) * ROWB
                                               + ks * 32 + (lane >> 4) * 16);
                LDSM4(ah, sa + ao);
                LDSM4(al, sal + ao);
            }
            #pragma unroll
            for (int nj = 0; nj < 8; nj++) {
                MMAH(acc[nj], ah, bh[nj]);
                MMAH(acc[nj], al, bh[nj]);
            }
        }
    }

    // epilogue
    const float* bias = GROUPED ? (bk + (size_t)cid * DD) : bias_plain;
    #pragma unroll
    for (int nj = 0; nj < 8; nj++) {
        const int col = n0 + warp_n * 64 + nj * 8 + (lane & 3) * 2;
        const float b0 = bias[col], b1 = bias[col + 1];
        const int r0 = m0 + warp_m * 16 + (lane >> 2);
        const size_t ro0 = GROUPED ? ((size_t)r0 * NNODE + nz) : (size_t)r0;
        const size_t ro1 = GROUPED ? ((size_t)(r0 + 8) * NNODE + nz) : (size_t)(r0 + 8);
        float v0 = acc[nj][0] + b0, v1 = acc[nj][1] + b1;
        float v2 = acc[nj][2] + b0, v3 = acc[nj][3] + b1;
        if (OUT == 2) {
            uint32_t hp, lp;
            hilo2h(v0, v1, hp, lp);
            *reinterpret_cast<uint32_t*>(Chi + ro0 * DD + col) = hp;
            *reinterpret_cast<uint32_t*>(Clo + ro0 * DD + col) = lp;
            hilo2h(v2, v3, hp, lp);
            *reinterpret_cast<uint32_t*>(Chi + ro1 * DD + col) = hp;
            *reinterpret_cast<uint32_t*>(Clo + ro1 * DD + col) = lp;
        } else if (OUT == 1) {
            __half2 h0; h0.x = __float2half_rn(v0); h0.y = __float2half_rn(v1);
            __half2 h1; h1.x = __float2half_rn(v2); h1.y = __float2half_rn(v3);
            *reinterpret_cast<__half2*>(Chi + ro0 * DD + col) = h0;
            *reinterpret_cast<__half2*>(Chi + ro1 * DD + col) = h1;
        } else {
            float2 w0; w0.x = v0; w0.y = v1;
            float2 w1; w1.x = v2; w1.y = v3;
            *reinterpret_cast<float2*>(Cf32 + ro0 * DD + col) = w0;
            *reinterpret_cast<float2*>(Cf32 + ro1 * DD + col) = w1;
        }
    }
}

// ================= tensor-core attention ======================================
// Block = (b,n,h), 384 threads (12 warps); warp w owns query rows [16w,16w+16).
// smem: Qhi, Qlo, Khi, Vhi (fp16), row stride 144B.
// S = (Qhi+Qlo)·Khi^T;  O = (Phi+Plo)·Vhi.  2-term fp16 splits.
#define AROW 144
#define ATEN (192 * AROW)            // 27648 per sub-tensor
#define ASMEM (4 * ATEN)             // 110592

__global__ __launch_bounds__(384, 1) void attn_mma_kernel() {
    extern __shared__ char smem[];
    const uint32_t sbase = smem_u32(smem);
    const int tid = threadIdx.x;
    const int lane = tid & 31, w = tid >> 5;

    const int bx = blockIdx.x;
    const int h = bx & 7;
    const int n = (bx >> 3) & 63;
    const int b = bx >> 9;
    const size_t base = ((size_t)b * TT * NNODE + n) * DD + h * DHH;
    const size_t tstride = (size_t)NNODE * DD;   // 32768

    // ---- stage Q hi/lo, K hi, V hi into smem ----
    {
        #pragma unroll
        for (int ti = 0; ti < 4; ti++) {
            const __half* tp = (ti == 0) ? (g_Qhi + base) : (ti == 1) ? (g_Qlo + base)
                             : (ti == 2) ? (g_Khi + base) : (g_Vhi + base);
            char* sp = smem + ti * ATEN;
            #pragma unroll
            for (int i = 0; i < 4; i++) {
                const int c = tid + i * 384;        // 0..1535
                const int r = c >> 3, o = c & 7;
                *reinterpret_cast<uint4*>(sp + r * AROW + o * 16) =
                    *reinterpret_cast<const uint4*>(tp + (size_t)r * tstride + o * 8);
            }
        }
    }
    __syncthreads();

    const uint32_t sQH = sbase, sQL = sbase + ATEN;
    const uint32_t sKH = sbase + 2 * ATEN;
    const uint32_t sVH = sbase + 3 * ATEN;

    // ---- preload Q fragments (16 rows x 64 k, hi+lo) ----
    uint32_t qh[4][4], ql[4][4];
    {
        const int qrow = w * 16 + (lane & 15);
        #pragma unroll
        for (int kt = 0; kt < 4; kt++) {
            const uint32_t ao = (uint32_t)(qrow * AROW + kt * 32 + (lane >> 4) * 16);
            LDSM4(qh[kt], sQH + ao);
            LDSM4(ql[kt], sQL + ao);
        }
    }

    float oacc[8][4];
    #pragma unroll
    for (int i = 0; i < 8; i++)
        #pragma unroll
        for (int j = 0; j < 4; j++) oacc[i][j] = 0.f;
    float m0 = -1e30f, m1 = -1e30f, l0 = 0.f, l1 = 0.f;

    for (int s0 = 0; s0 < TT; s0 += 16) {
        // ---- S = Q K^T (2-term) ----
        float sa0[4] = {0.f, 0.f, 0.f, 0.f};
        float sa1[4] = {0.f, 0.f, 0.f, 0.f};
        #pragma unroll
        for (int kt = 0; kt < 4; kt++) {
            const uint32_t bo = (uint32_t)((s0 + ((lane >> 4) << 3) + (lane & 7)) * AROW
                                           + kt * 32 + ((lane >> 3) & 1) * 16);
            uint32_t rh[4];
            LDSM4(rh, sKH + bo);
            uint32_t bh0[2] = {rh[0], rh[1]}, bh1[2] = {rh[2], rh[3]};
            MMAH(sa0, qh[kt], bh0);
            MMAH(sa0, ql[kt], bh0);
            MMAH(sa1, qh[kt], bh1);
            MMAH(sa1, ql[kt], bh1);
        }
        // ---- online softmax ----
        const float sc = 0.125f;
        #pragma unroll
        for (int i = 0; i < 4; i++) { sa0[i] *= sc; sa1[i] *= sc; }
        float r0m = fmaxf(fmaxf(sa0[0], sa0[1]), fmaxf(sa1[0], sa1[1]));
        float r1m = fmaxf(fmaxf(sa0[2], sa0[3]), fmaxf(sa1[2], sa1[3]));
        r0m = fmaxf(r0m, __shfl_xor_sync(0xffffffffu, r0m, 1));
        r0m = fmaxf(r0m, __shfl_xor_sync(0xffffffffu, r0m, 2));
        r1m = fmaxf(r1m, __shfl_xor_sync(0xffffffffu, r1m, 1));
        r1m = fmaxf(r1m, __shfl_xor_sync(0xffffffffu, r1m, 2));
        const float mn0 = fmaxf(m0, r0m), mn1 = fmaxf(m1, r1m);
        const float al0 = __expf(m0 - mn0), al1 = __expf(m1 - mn1);
        m0 = mn0; m1 = mn1;
        float p[8];
        p[0] = __expf(sa0[0] - mn0); p[1] = __expf(sa0[1] - mn0);
        p[2] = __expf(sa1[0] - mn0); p[3] = __expf(sa1[1] - mn0);
        p[4] = __expf(sa0[2] - mn1); p[5] = __expf(sa0[3] - mn1);
        p[6] = __expf(sa1[2] - mn1); p[7] = __expf(sa1[3] - mn1);
        float rs0 = p[0] + p[1] + p[2] + p[3];
        float rs1 = p[4] + p[5] + p[6] + p[7];
        rs0 += __shfl_xor_sync(0xffffffffu, rs0, 1);
        rs0 += __shfl_xor_sync(0xffffffffu, rs0, 2);
        rs1 += __shfl_xor_sync(0xffffffffu, rs1, 1);
        rs1 += __shfl_xor_sync(0xffffffffu, rs1, 2);
        l0 = l0 * al0 + rs0;
        l1 = l1 * al1 + rs1;
        #pragma unroll
        for (int nt = 0; nt < 8; nt++) {
            oacc[nt][0] *= al0; oacc[nt][1] *= al0;
            oacc[nt][2] *= al1; oacc[nt][3] *= al1;
        }
        // ---- pack P into A-fragments (fp16 hi/lo) ----
        uint32_t ph[4], pl[4];
        hilo2h(p[0], p[1], ph[0], pl[0]);
        hilo2h(p[4], p[5], ph[1], pl[1]);
        hilo2h(p[2], p[3], ph[2], pl[2]);
        hilo2h(p[6], p[7], ph[3], pl[3]);
        // ---- O += P V (2-term) ----
        #pragma unroll
        for (int nt = 0; nt < 4; nt++) {
            const uint32_t vo = (uint32_t)((s0 + ((lane >> 3) & 1) * 8 + (lane & 7)) * AROW
                                           + nt * 32 + (lane >> 4) * 16);
            uint32_t rh[4];
            LDSM4T(rh, sVH + vo);
            uint32_t bh0[2] = {rh[0], rh[1]}, bh1[2] = {rh[2], rh[3]};
            MMAH(oacc[2*nt],   ph, bh0);
            MMAH(oacc[2*nt],   pl, bh0);
            MMAH(oacc[2*nt+1], ph, bh1);
            MMAH(oacc[2*nt+1], pl, bh1);
        }
    }

    // ---- normalize + store O as fp16 hi/lo ----
    const float inv0 = 1.f / l0, inv1 = 1.f / l1;
    const int r0 = w * 16 + (lane >> 2);
    const int c0 = (lane & 3) * 2;
    const size_t g0 = base + (size_t)r0 * tstride;
    const size_t g1 = g0 + 8 * tstride;
    #pragma unroll
    for (int nt = 0; nt < 8; nt++) {
        const int col = nt * 8 + c0;
        uint32_t hp, lp;
        hilo2h(oacc[nt][0] * inv0, oacc[nt][1] * inv0, hp, lp);
        *reinterpret_cast<uint32_t*>(g_Ohi + g0 + col) = hp;
        *reinterpret_cast<uint32_t*>(g_Olo + g0 + col) = lp;
        hilo2h(oacc[nt][2] * inv1, oacc[nt][3] * inv1, hp, lp);
        *reinterpret_cast<uint32_t*>(g_Ohi + g1 + col) = hp;
        *reinterpret_cast<uint32_t*>(g_Olo + g1 + col) = lp;
    }
}

// -------------------------------------------------------------------------------
extern "C" void kernel_launch(void* const* d_in, const int* in_sizes, int n_in,
                              void* d_out, int out_size) {
    const float* x      = (const float*)d_in[0];
    const float* Wq_w   = (const float*)d_in[1];
    const float* Wq_b   = (const float*)d_in[2];
    const float* Wv_w   = (const float*)d_in[3];
    const float* Wv_b   = (const float*)d_in[4];
    const float* Wk     = (const float*)d_in[5];
    const float* bk     = (const float*)d_in[6];
    const float* proj_w = (const float*)d_in[7];
    const float* proj_b = (const float*)d_in[8];
    const int*   cidraw = (const int*)d_in[9];
    float* out = (float*)d_out;

    (void)in_sizes; (void)n_in; (void)out_size;

    void *pXhi, *pXlo, *pQhi, *pQlo, *pKhi, *pVhi, *pOhi, *pOlo;
    cudaGetSymbolAddress(&pXhi, g_Xhi);
    cudaGetSymbolAddress(&pXlo, g_Xlo);
    cudaGetSymbolAddress(&pQhi, g_Qhi);
    cudaGetSymbolAddress(&pQlo, g_Qlo);
    cudaGetSymbolAddress(&pKhi, g_Khi);
    cudaGetSymbolAddress(&pVhi, g_Vhi);
    cudaGetSymbolAddress(&pOhi, g_Ohi);
    cudaGetSymbolAddress(&pOlo, g_Olo);

    cudaFuncSetAttribute(attn_mma_kernel,
                         cudaFuncAttributeMaxDynamicSharedMemorySize, ASMEM);
    cudaFuncSetAttribute(gemm_mma_kernel<0,2>,
                         cudaFuncAttributeMaxDynamicSharedMemorySize, SMEM_GEMM);
    cudaFuncSetAttribute(gemm_mma_kernel<0,1>,
                         cudaFuncAttributeMaxDynamicSharedMemorySize, SMEM_GEMM);
    cudaFuncSetAttribute(gemm_mma_kernel<1,1>,
                         cudaFuncAttributeMaxDynamicSharedMemorySize, SMEM_GEMM);
    cudaFuncSetAttribute(gemm_mma_kernel<0,0>,
                         cudaFuncAttributeMaxDynamicSharedMemorySize, SMEM_GEMM);

    decode_cid_kernel<<<1, 1>>>(cidraw);
    convert_weights_kernel<<<(NW * DD * DD) / 256, 256>>>(Wq_w, Wv_w, proj_w, Wk);
    convert_x_kernel<<<(M_TOTAL * (size_t)DD) / 1024, 256>>>(x);

    dim3 gp(4, M_TOTAL / 64);                  // n-fastest for L2 reuse of A
    gemm_mma_kernel<0,2><<<gp, 256, SMEM_GEMM>>>(
        (const __half*)pXhi, (const __half*)pXlo,
        Wq_b, nullptr, nullptr,
        (__half*)pQhi, (__half*)pQlo, 0);
    gemm_mma_kernel<0,1><<<gp, 256, SMEM_GEMM>>>(
        (const __half*)pXhi, (const __half*)pXlo,
        Wv_b, nullptr, nullptr,
        (__half*)pVhi, nullptr, 1);

    dim3 gk(4, BT / 64, NNODE);
    gemm_mma_kernel<1,1><<<gk, 256, SMEM_GEMM>>>(
        (const __half*)pXhi, (const __half*)pXlo,
        nullptr, bk, nullptr,
        (__half*)pKhi, nullptr, -1);

    attn_mma_kernel<<<BB * NNODE * HH, 384, ASMEM>>>();   // 4096 blocks

    gemm_mma_kernel<0,0><<<gp, 256, SMEM_GEMM>>>(
        (const __half*)pOhi, (const __half*)pOlo,
        proj_b, nullptr, out, nullptr, nullptr, 2);
}